// round 2
// baseline (speedup 1.0000x reference)
#include <cuda_runtime.h>
#include <cstdint>

// ---------------------------------------------------------------------------
// Problem: B=1, T=262144, D=8, H=64, A=4
//   mask = any(x != 0, axis=-1)
//   h1 = tanh(x@W1+b1); h2 = tanh(h1@W2+b2); xz = h2@Wx + b_rnn
//   h_t = mask_t ? tanh(xz_t + h_{t-1}@Wh) : h_{t-1}   (h_0 = 0)
//   means = hs@Wm + bm
// Inputs (metadata order): x, W1, b1, W2, b2, Wx, Wh, b_rnn, Wm, bm
// Output: means [T,4] float32
// ---------------------------------------------------------------------------

#define MAX_T 262144
#define H 64

__device__ float g_xz[MAX_T * H];    // 64 MB
__device__ float g_mask[MAX_T];      // 1 MB
__device__ float g_hs[MAX_T * H];    // 64 MB

// Accurate-enough fast tanh: e = 2^(-2|v|*log2 e) = exp(-2|v|);
// tanh(|v|) = (1-e)/(1+e); restore sign. rel err ~2^-22 from MUFU.EX2/RCP.
__device__ __forceinline__ float tanh_fast(float v) {
    float a = fabsf(v) * -2.8853900817779268f;   // -2*log2(e)*|v|
    float e;
    asm("ex2.approx.f32 %0, %1;" : "=f"(e) : "f"(a));
    float r;
    asm("rcp.approx.f32 %0, %1;" : "=f"(r) : "f"(e + 1.0f));
    float t = (1.0f - e) * r;
    return copysignf(t, v);
}

// ---------------------------------------------------------------------------
// Kernel 1: encoder. One thread per timestep, weights staged in shared memory,
// float4-vectorized broadcast LDS.
// ---------------------------------------------------------------------------
__global__ void __launch_bounds__(128) encoder_kernel(
    const float* __restrict__ x,
    const float* __restrict__ W1, const float* __restrict__ b1,
    const float* __restrict__ W2, const float* __restrict__ b2,
    const float* __restrict__ Wx, const float* __restrict__ brnn,
    int T)
{
    __shared__ __align__(16) float sW1[8 * 64];
    __shared__ __align__(16) float sW2[64 * 64];
    __shared__ __align__(16) float sWx[64 * 64];
    __shared__ __align__(16) float sb1[64];
    __shared__ __align__(16) float sb2[64];
    __shared__ __align__(16) float sbr[64];

    for (int i = threadIdx.x; i < 8 * 64; i += 128) sW1[i] = W1[i];
    for (int i = threadIdx.x; i < 64 * 64; i += 128) { sW2[i] = W2[i]; sWx[i] = Wx[i]; }
    if (threadIdx.x < 64) {
        sb1[threadIdx.x] = b1[threadIdx.x];
        sb2[threadIdx.x] = b2[threadIdx.x];
        sbr[threadIdx.x] = brnn[threadIdx.x];
    }
    __syncthreads();

    const float4* sW1v = (const float4*)sW1;
    const float4* sW2v = (const float4*)sW2;
    const float4* sWxv = (const float4*)sWx;

    for (long t = (long)blockIdx.x * 128 + threadIdx.x; t < T;
         t += (long)gridDim.x * 128) {
        float4 xa = ((const float4*)x)[t * 2];
        float4 xb = ((const float4*)x)[t * 2 + 1];
        float xv[8] = {xa.x, xa.y, xa.z, xa.w, xb.x, xb.y, xb.z, xb.w};

        bool nz = (xa.x != 0.f) | (xa.y != 0.f) | (xa.z != 0.f) | (xa.w != 0.f) |
                  (xb.x != 0.f) | (xb.y != 0.f) | (xb.z != 0.f) | (xb.w != 0.f);
        g_mask[t] = nz ? 1.0f : 0.0f;

        // ---- h1 = tanh(x @ W1 + b1) ----
        float h1[64];
        {
            float4 acc[16];
            #pragma unroll
            for (int q = 0; q < 16; q++) acc[q] = ((const float4*)sb1)[q];
            #pragma unroll
            for (int d = 0; d < 8; d++) {
                float xd = xv[d];
                #pragma unroll
                for (int q = 0; q < 16; q++) {
                    float4 w = sW1v[d * 16 + q];
                    acc[q].x = fmaf(xd, w.x, acc[q].x);
                    acc[q].y = fmaf(xd, w.y, acc[q].y);
                    acc[q].z = fmaf(xd, w.z, acc[q].z);
                    acc[q].w = fmaf(xd, w.w, acc[q].w);
                }
            }
            #pragma unroll
            for (int q = 0; q < 16; q++) {
                h1[4 * q + 0] = tanh_fast(acc[q].x);
                h1[4 * q + 1] = tanh_fast(acc[q].y);
                h1[4 * q + 2] = tanh_fast(acc[q].z);
                h1[4 * q + 3] = tanh_fast(acc[q].w);
            }
        }

        // ---- h2 = tanh(h1 @ W2 + b2), two 32-wide halves to bound registers ----
        float h2[64];
        #pragma unroll
        for (int hf = 0; hf < 2; hf++) {
            float4 acc[8];
            #pragma unroll
            for (int q = 0; q < 8; q++) acc[q] = ((const float4*)sb2)[hf * 8 + q];
            #pragma unroll
            for (int k = 0; k < 64; k++) {
                float hk = h1[k];
                #pragma unroll
                for (int q = 0; q < 8; q++) {
                    float4 w = sW2v[k * 16 + hf * 8 + q];
                    acc[q].x = fmaf(hk, w.x, acc[q].x);
                    acc[q].y = fmaf(hk, w.y, acc[q].y);
                    acc[q].z = fmaf(hk, w.z, acc[q].z);
                    acc[q].w = fmaf(hk, w.w, acc[q].w);
                }
            }
            #pragma unroll
            for (int q = 0; q < 8; q++) {
                h2[hf * 32 + 4 * q + 0] = tanh_fast(acc[q].x);
                h2[hf * 32 + 4 * q + 1] = tanh_fast(acc[q].y);
                h2[hf * 32 + 4 * q + 2] = tanh_fast(acc[q].z);
                h2[hf * 32 + 4 * q + 3] = tanh_fast(acc[q].w);
            }
        }

        // ---- xz = h2 @ Wx + b_rnn ----
        float4* op = (float4*)(g_xz + (size_t)t * 64);
        #pragma unroll
        for (int hf = 0; hf < 2; hf++) {
            float4 acc[8];
            #pragma unroll
            for (int q = 0; q < 8; q++) acc[q] = ((const float4*)sbr)[hf * 8 + q];
            #pragma unroll
            for (int k = 0; k < 64; k++) {
                float hk = h2[k];
                #pragma unroll
                for (int q = 0; q < 8; q++) {
                    float4 w = sWxv[k * 16 + hf * 8 + q];
                    acc[q].x = fmaf(hk, w.x, acc[q].x);
                    acc[q].y = fmaf(hk, w.y, acc[q].y);
                    acc[q].z = fmaf(hk, w.z, acc[q].z);
                    acc[q].w = fmaf(hk, w.w, acc[q].w);
                }
            }
            #pragma unroll
            for (int q = 0; q < 8; q++) op[hf * 8 + q] = acc[q];
        }
    }
}

// ---------------------------------------------------------------------------
// Kernel 2: sequential scan. Single block, 64 threads; thread j owns h[j] and
// holds Wh column j in registers. h broadcast via double-buffered shared array,
// one __syncthreads per step. xz/mask prefetched PF steps ahead (register ring)
// so global latency hides in dependency stalls.
// ---------------------------------------------------------------------------
#define PF 8

__global__ void __launch_bounds__(64, 1) scan_kernel(
    const float* __restrict__ Wh, int T)
{
    const int j = threadIdx.x;

    float wh[64];
    #pragma unroll
    for (int k = 0; k < 64; k++) wh[k] = Wh[k * 64 + j];

    __shared__ __align__(16) float hbuf[2][64];
    hbuf[0][j] = 0.0f;

    float zq[PF], mq[PF];
    #pragma unroll
    for (int s = 0; s < PF; s++) {
        if (s < T) { zq[s] = g_xz[(size_t)s * 64 + j]; mq[s] = g_mask[s]; }
        else       { zq[s] = 0.0f; mq[s] = 0.0f; }
    }
    __syncthreads();

    float h = 0.0f;
    const int Tmain = T & ~(PF - 1);

    for (int t0 = 0; t0 < Tmain; t0 += PF) {
        #pragma unroll
        for (int s = 0; s < PF; s++) {
            const int t = t0 + s;
            const int p = s & 1;                 // t0 is even multiple of PF
            float z = zq[s];
            float m = mq[s];
            const int tp = t + PF;
            if (tp < T) {                        // prefetch (off critical path)
                zq[s] = g_xz[(size_t)tp * 64 + j];
                mq[s] = g_mask[tp];
            }

            const float4* hv = (const float4*)(&hbuf[p][0]);
            float a0 = z, a1 = 0.f, a2 = 0.f, a3 = 0.f;
            float a4 = 0.f, a5 = 0.f, a6 = 0.f, a7 = 0.f;
            #pragma unroll
            for (int k4 = 0; k4 < 16; k4++) {
                float4 hh = hv[k4];
                const int k = 4 * k4;
                if (k4 & 1) {
                    a4 = fmaf(hh.x, wh[k + 0], a4);
                    a5 = fmaf(hh.y, wh[k + 1], a5);
                    a6 = fmaf(hh.z, wh[k + 2], a6);
                    a7 = fmaf(hh.w, wh[k + 3], a7);
                } else {
                    a0 = fmaf(hh.x, wh[k + 0], a0);
                    a1 = fmaf(hh.y, wh[k + 1], a1);
                    a2 = fmaf(hh.z, wh[k + 2], a2);
                    a3 = fmaf(hh.w, wh[k + 3], a3);
                }
            }
            float sum = ((a0 + a4) + (a1 + a5)) + ((a2 + a6) + (a3 + a7));
            float hn = tanh_fast(sum);
            h = fmaf(m, hn - h, h);              // masked carry
            g_hs[(size_t)t * 64 + j] = h;        // fire-and-forget
            hbuf[p ^ 1][j] = h;
            __syncthreads();
        }
    }
    // tail (T not multiple of PF); zq slot s holds xz[Tmain+s] already
    for (int t = Tmain; t < T; t++) {
        const int s = t - Tmain;
        const int p = t & 1;
        float z = zq[s];
        float m = mq[s];
        const float4* hv = (const float4*)(&hbuf[p][0]);
        float a0 = z, a1 = 0.f, a2 = 0.f, a3 = 0.f;
        #pragma unroll
        for (int k4 = 0; k4 < 16; k4++) {
            float4 hh = hv[k4];
            const int k = 4 * k4;
            a0 = fmaf(hh.x, wh[k + 0], a0);
            a1 = fmaf(hh.y, wh[k + 1], a1);
            a2 = fmaf(hh.z, wh[k + 2], a2);
            a3 = fmaf(hh.w, wh[k + 3], a3);
        }
        float sum = (a0 + a1) + (a2 + a3);
        float hn = tanh_fast(sum);
        h = fmaf(m, hn - h, h);
        g_hs[(size_t)t * 64 + j] = h;
        hbuf[p ^ 1][j] = h;
        __syncthreads();
    }
}

// ---------------------------------------------------------------------------
// Kernel 3: means = hs @ Wm + bm. Memory-bound 64MB stream.
// ---------------------------------------------------------------------------
__global__ void __launch_bounds__(256) means_kernel(
    const float* __restrict__ Wm, const float* __restrict__ bm,
    float4* __restrict__ out, int T)
{
    __shared__ __align__(16) float4 sWm[64];
    if (threadIdx.x < 64) sWm[threadIdx.x] = ((const float4*)Wm)[threadIdx.x];
    __syncthreads();
    float4 bmv = *(const float4*)bm;

    for (int t = blockIdx.x * 256 + threadIdx.x; t < T; t += gridDim.x * 256) {
        const float4* hr = (const float4*)(g_hs + (size_t)t * 64);
        float4 acc = bmv;
        #pragma unroll
        for (int q = 0; q < 16; q++) {
            float4 hh = hr[q];
            float4 w0 = sWm[4 * q + 0];
            float4 w1 = sWm[4 * q + 1];
            float4 w2 = sWm[4 * q + 2];
            float4 w3 = sWm[4 * q + 3];
            acc.x = fmaf(hh.x, w0.x, acc.x); acc.y = fmaf(hh.x, w0.y, acc.y);
            acc.z = fmaf(hh.x, w0.z, acc.z); acc.w = fmaf(hh.x, w0.w, acc.w);
            acc.x = fmaf(hh.y, w1.x, acc.x); acc.y = fmaf(hh.y, w1.y, acc.y);
            acc.z = fmaf(hh.y, w1.z, acc.z); acc.w = fmaf(hh.y, w1.w, acc.w);
            acc.x = fmaf(hh.z, w2.x, acc.x); acc.y = fmaf(hh.z, w2.y, acc.y);
            acc.z = fmaf(hh.z, w2.z, acc.z); acc.w = fmaf(hh.z, w2.w, acc.w);
            acc.x = fmaf(hh.w, w3.x, acc.x); acc.y = fmaf(hh.w, w3.y, acc.y);
            acc.z = fmaf(hh.w, w3.z, acc.z); acc.w = fmaf(hh.w, w3.w, acc.w);
        }
        out[t] = acc;
    }
}

// ---------------------------------------------------------------------------
extern "C" void kernel_launch(void* const* d_in, const int* in_sizes, int n_in,
                              void* d_out, int out_size)
{
    const float* x    = (const float*)d_in[0];
    const float* W1   = (const float*)d_in[1];
    const float* b1   = (const float*)d_in[2];
    const float* W2   = (const float*)d_in[3];
    const float* b2   = (const float*)d_in[4];
    const float* Wx   = (const float*)d_in[5];
    const float* Wh   = (const float*)d_in[6];
    const float* brnn = (const float*)d_in[7];
    const float* Wm   = (const float*)d_in[8];
    const float* bm   = (const float*)d_in[9];

    int T = in_sizes[0] / 8;   // x is [1, T, 8]
    if (T > MAX_T) T = MAX_T;

    int enc_blocks = (T + 127) / 128;
    if (enc_blocks > 2048) enc_blocks = 2048;

    encoder_kernel<<<enc_blocks, 128>>>(x, W1, b1, W2, b2, Wx, brnn, T);
    scan_kernel<<<1, 64>>>(Wh, T);
    means_kernel<<<1024, 256>>>(Wm, bm, (float4*)d_out, T);
}